// round 1
// baseline (speedup 1.0000x reference)
#include <cuda_runtime.h>
#include <cstdint>

// Problem constants (match reference)
#define NATOMS   100000
#define NPAIRS   16000000
#define CUTOFF2  0.81f
#define PREFAC   138.93544539709032f

// Packed atom data: two float4 per atom, 32B aligned => one 32B L2 sector per atom touch.
// slot 2*i   : (x, y, z, charge)
// slot 2*i+1 : (sigma, epsilon, 0, 0)
__device__ float4 g_atoms[2 * NATOMS];

__global__ void pack_kernel(const float* __restrict__ coords,
                            const float* __restrict__ charges,
                            const float* __restrict__ sigma,
                            const float* __restrict__ epsilon,
                            float* __restrict__ out)
{
    int i = blockIdx.x * blockDim.x + threadIdx.x;
    if (i == 0) out[0] = 0.0f;   // d_out is poisoned; zero it here (ordered before energy kernel)
    if (i < NATOMS) {
        float4 a;
        a.x = coords[3 * i + 0];
        a.y = coords[3 * i + 1];
        a.z = coords[3 * i + 2];
        a.w = charges[i];
        g_atoms[2 * i] = a;
        float4 b;
        b.x = sigma[i];
        b.y = epsilon[i];
        b.z = 0.0f;
        b.w = 0.0f;
        g_atoms[2 * i + 1] = b;
    }
}

__global__ __launch_bounds__(256) void energy_kernel(const int2* __restrict__ pairs,
                                                     const float* __restrict__ box,
                                                     float* __restrict__ out,
                                                     int npairs)
{
    // Box diagonal (eye * L in the reference, but read the real diagonal)
    const float bx = __ldg(box + 0);
    const float by = __ldg(box + 4);
    const float bz = __ldg(box + 8);
    const float ibx = 1.0f / bx;
    const float iby = 1.0f / by;
    const float ibz = 1.0f / bz;

    float acc = 0.0f;

    const int stride = gridDim.x * blockDim.x;
    for (int idx = blockIdx.x * blockDim.x + threadIdx.x; idx < npairs; idx += stride) {
        int2 p = __ldg(pairs + idx);
        const int i = p.x;
        const int j = p.y;

        const float4 ai = __ldg(&g_atoms[2 * i]);
        const float4 aj = __ldg(&g_atoms[2 * j]);

        float dx = ai.x - aj.x;
        float dy = ai.y - aj.y;
        float dz = ai.z - aj.z;
        // minimum image: d - L * round(d / L); rintf == round-half-to-even == jnp.round
        dx -= bx * rintf(dx * ibx);
        dy -= by * rintf(dy * iby);
        dz -= bz * rintf(dz * ibz);

        const float r2 = dx * dx + dy * dy + dz * dz;

        const bool valid = ((i / 3) != (j / 3)) && (r2 < CUTOFF2) && (i != j);
        if (valid) {
            const float4 bi = __ldg(&g_atoms[2 * i + 1]);  // same 32B sector as ai -> L1 hit
            const float4 bj = __ldg(&g_atoms[2 * j + 1]);

            const float inv_r  = rsqrtf(r2);
            const float inv_r2 = 1.0f / r2;

            const float e_coul = PREFAC * ai.w * aj.w * inv_r;

            const float sig = 0.5f * (bi.x + bj.x);
            const float eps = sqrtf(bi.y * bj.y);
            const float sr2 = sig * sig * inv_r2;
            const float sr6 = sr2 * sr2 * sr2;
            const float e_lj = 4.0f * eps * (sr6 * sr6 - sr6);

            acc += e_coul + e_lj;
        }
    }

    // warp reduction
    #pragma unroll
    for (int off = 16; off > 0; off >>= 1)
        acc += __shfl_down_sync(0xFFFFFFFFu, acc, off);

    // block reduction via shared memory
    __shared__ float warp_sums[8];  // 256 threads / 32
    const int lane = threadIdx.x & 31;
    const int wid  = threadIdx.x >> 5;
    if (lane == 0) warp_sums[wid] = acc;
    __syncthreads();

    if (wid == 0) {
        float v = (lane < (blockDim.x >> 5)) ? warp_sums[lane] : 0.0f;
        #pragma unroll
        for (int off = 4; off > 0; off >>= 1)
            v += __shfl_down_sync(0xFFFFFFFFu, v, off);
        if (lane == 0)
            atomicAdd(out, v);
    }
}

extern "C" void kernel_launch(void* const* d_in, const int* in_sizes, int n_in,
                              void* d_out, int out_size)
{
    const float* coords  = (const float*)d_in[0];  // [N,3]
    const float* box     = (const float*)d_in[1];  // [3,3]
    const float* charges = (const float*)d_in[2];  // [N]
    const float* sigma   = (const float*)d_in[3];  // [N]
    const float* epsilon = (const float*)d_in[4];  // [N]
    const int2*  pairs   = (const int2*)d_in[5];   // [NPAIRS,2]
    float* out = (float*)d_out;

    const int npairs = in_sizes[5] / 2;

    // Pack atoms + zero output
    {
        const int threads = 256;
        const int blocks = (NATOMS + threads - 1) / threads;
        pack_kernel<<<blocks, threads>>>(coords, charges, sigma, epsilon, out);
    }

    // Energy reduction
    {
        const int threads = 256;
        const int blocks = 4096;  // ~27 SMs-waves of grid-stride work, ~3.9K pairs per block
        energy_kernel<<<blocks, threads>>>(pairs, box, out, npairs);
    }
}

// round 2
// speedup vs baseline: 1.0524x; 1.0524x over previous
#include <cuda_runtime.h>
#include <cstdint>

// Problem constants (match reference)
#define NATOMS   100000
#define CUTOFF2  0.81f
#define PREFAC   138.93544539709032f

// Packed atom data: two float4 per atom, 32B aligned => one 32B L2 sector per atom touch.
// slot 2*i   : (x, y, z, charge)
// slot 2*i+1 : (sigma, epsilon, 0, 0)
__device__ float4 g_atoms[2 * NATOMS];

__global__ void pack_kernel(const float* __restrict__ coords,
                            const float* __restrict__ charges,
                            const float* __restrict__ sigma,
                            const float* __restrict__ epsilon,
                            float* __restrict__ out)
{
    int i = blockIdx.x * blockDim.x + threadIdx.x;
    if (i == 0) out[0] = 0.0f;   // d_out is poisoned; zero it here (ordered before energy kernel)
    if (i < NATOMS) {
        float4 a;
        a.x = coords[3 * i + 0];
        a.y = coords[3 * i + 1];
        a.z = coords[3 * i + 2];
        a.w = charges[i];
        g_atoms[2 * i] = a;
        float4 b;
        b.x = sigma[i];
        b.y = epsilon[i];
        b.z = 0.0f;
        b.w = 0.0f;
        g_atoms[2 * i + 1] = b;
    }
}

// Per-pair tail math, executed only for the ~0.3% of pairs inside the cutoff.
__device__ __forceinline__ float pair_energy(int i, int j, float r2,
                                             float qi, float qj)
{
    const float4 bi = __ldg(&g_atoms[2 * i + 1]);  // same 32B sector as coords -> L1 hit
    const float4 bj = __ldg(&g_atoms[2 * j + 1]);

    const float inv_r  = rsqrtf(r2);
    const float inv_r2 = 1.0f / r2;

    const float e_coul = PREFAC * qi * qj * inv_r;

    const float sig = 0.5f * (bi.x + bj.x);
    const float eps = sqrtf(bi.y * bj.y);
    const float sr2 = sig * sig * inv_r2;
    const float sr6 = sr2 * sr2 * sr2;
    return fmaf(4.0f * eps, sr6 * sr6 - sr6, e_coul);
}

__global__ __launch_bounds__(256) void energy_kernel(const int4* __restrict__ pairs2,
                                                     const float* __restrict__ box,
                                                     float* __restrict__ out,
                                                     int npairs2)  // number of int4 (2 pairs each)
{
    const float bx = __ldg(box + 0);
    const float by = __ldg(box + 4);
    const float bz = __ldg(box + 8);
    const float ibx = 1.0f / bx;
    const float iby = 1.0f / by;
    const float ibz = 1.0f / bz;

    float acc = 0.0f;

    const int stride = gridDim.x * blockDim.x;
    for (int idx = blockIdx.x * blockDim.x + threadIdx.x; idx < npairs2; idx += stride) {
        const int4 p = __ldg(pairs2 + idx);
        const int i0 = p.x, j0 = p.y;
        const int i1 = p.z, j1 = p.w;

        // Issue all four divergent gathers back-to-back (MLP=4) before any compute.
        const float4 ai0 = __ldg(&g_atoms[2 * i0]);
        const float4 aj0 = __ldg(&g_atoms[2 * j0]);
        const float4 ai1 = __ldg(&g_atoms[2 * i1]);
        const float4 aj1 = __ldg(&g_atoms[2 * j1]);

        // ---- pair 0 ----
        {
            float dx = ai0.x - aj0.x;
            float dy = ai0.y - aj0.y;
            float dz = ai0.z - aj0.z;
            dx -= bx * rintf(dx * ibx);
            dy -= by * rintf(dy * iby);
            dz -= bz * rintf(dz * ibz);
            const float r2 = fmaf(dx, dx, fmaf(dy, dy, dz * dz));
            if ((r2 < CUTOFF2) && ((i0 / 3) != (j0 / 3)) && (i0 != j0))
                acc += pair_energy(i0, j0, r2, ai0.w, aj0.w);
        }
        // ---- pair 1 ----
        {
            float dx = ai1.x - aj1.x;
            float dy = ai1.y - aj1.y;
            float dz = ai1.z - aj1.z;
            dx -= bx * rintf(dx * ibx);
            dy -= by * rintf(dy * iby);
            dz -= bz * rintf(dz * ibz);
            const float r2 = fmaf(dx, dx, fmaf(dy, dy, dz * dz));
            if ((r2 < CUTOFF2) && ((i1 / 3) != (j1 / 3)) && (i1 != j1))
                acc += pair_energy(i1, j1, r2, ai1.w, aj1.w);
        }
    }

    // warp reduction
    #pragma unroll
    for (int off = 16; off > 0; off >>= 1)
        acc += __shfl_down_sync(0xFFFFFFFFu, acc, off);

    // block reduction via shared memory
    __shared__ float warp_sums[8];
    const int lane = threadIdx.x & 31;
    const int wid  = threadIdx.x >> 5;
    if (lane == 0) warp_sums[wid] = acc;
    __syncthreads();

    if (wid == 0) {
        float v = (lane < (blockDim.x >> 5)) ? warp_sums[lane] : 0.0f;
        #pragma unroll
        for (int off = 4; off > 0; off >>= 1)
            v += __shfl_down_sync(0xFFFFFFFFu, v, off);
        if (lane == 0)
            atomicAdd(out, v);
    }
}

extern "C" void kernel_launch(void* const* d_in, const int* in_sizes, int n_in,
                              void* d_out, int out_size)
{
    const float* coords  = (const float*)d_in[0];  // [N,3]
    const float* box     = (const float*)d_in[1];  // [3,3]
    const float* charges = (const float*)d_in[2];  // [N]
    const float* sigma   = (const float*)d_in[3];  // [N]
    const float* epsilon = (const float*)d_in[4];  // [N]
    const int4*  pairs2  = (const int4*)d_in[5];   // [NPAIRS,2] viewed as [NPAIRS/2, 4]
    float* out = (float*)d_out;

    const int npairs2 = in_sizes[5] / 4;  // 16M pairs -> 8M int4

    {
        const int threads = 256;
        const int blocks = (NATOMS + threads - 1) / threads;
        pack_kernel<<<blocks, threads>>>(coords, charges, sigma, epsilon, out);
    }
    {
        const int threads = 256;
        const int blocks = 4096;  // 1M threads, 8 unrolled iterations each
        energy_kernel<<<blocks, threads>>>(pairs2, box, out, npairs2);
    }
}

// round 3
// speedup vs baseline: 1.3673x; 1.2992x over previous
#include <cuda_runtime.h>
#include <cstdint>

#define NATOMS   100000
#define CUTOFF2  0.81f
#define PREFAC   138.93544539709032f

// Packed atom data: two float4 per atom, 32B aligned => one 32B L2 sector per atom.
// slot 2*i   : (x, y, z, charge)
// slot 2*i+1 : (sigma, epsilon, 0, 0)
__device__ float4 g_atoms[2 * NATOMS];

__global__ void pack_kernel(const float* __restrict__ coords,
                            const float* __restrict__ charges,
                            const float* __restrict__ sigma,
                            const float* __restrict__ epsilon,
                            float* __restrict__ out)
{
    int i = blockIdx.x * blockDim.x + threadIdx.x;
    if (i == 0) out[0] = 0.0f;   // zero the poisoned output (ordered before energy kernel)
    if (i < NATOMS) {
        float4 a;
        a.x = coords[3 * i + 0];
        a.y = coords[3 * i + 1];
        a.z = coords[3 * i + 2];
        a.w = charges[i];
        g_atoms[2 * i] = a;
        float4 b;
        b.x = sigma[i];
        b.y = epsilon[i];
        b.z = 0.0f;
        b.w = 0.0f;
        g_atoms[2 * i + 1] = b;
    }
}

// Tail math: only for pairs inside the cutoff (~0.3%).
// Second atom-record halves are same-sector L1 hits.
__device__ __forceinline__ float pair_energy(int i, int j, float r2,
                                             float qi, float qj)
{
    const float4 bi = __ldg(&g_atoms[2 * i + 1]);
    const float4 bj = __ldg(&g_atoms[2 * j + 1]);

    const float inv_r  = rsqrtf(r2);
    const float inv_r2 = 1.0f / r2;

    const float e_coul = PREFAC * qi * qj * inv_r;

    const float sig = 0.5f * (bi.x + bj.x);
    const float eps = sqrtf(bi.y * bj.y);
    const float sr2 = sig * sig * inv_r2;
    const float sr6 = sr2 * sr2 * sr2;
    return fmaf(4.0f * eps, sr6 * sr6 - sr6, e_coul);
}

__global__ __launch_bounds__(256, 8) void energy_kernel(const int4* __restrict__ pairs2,
                                                        const float* __restrict__ box,
                                                        float* __restrict__ out,
                                                        int npairs2)
{
    // Uniform values -> expect UR allocation, not GPR pressure.
    const float bx = __ldg(box + 0);
    const float by = __ldg(box + 4);
    const float bz = __ldg(box + 8);
    const float ibx = 1.0f / bx;
    const float iby = 1.0f / by;
    const float ibz = 1.0f / bz;

    float acc = 0.0f;

    const int stride = gridDim.x * blockDim.x;
    for (int idx = blockIdx.x * blockDim.x + threadIdx.x; idx < npairs2; idx += stride) {
        const int4 p = __ldcs(pairs2 + idx);   // streaming: evict-first, keep L1 for atoms

        // Four divergent gathers back-to-back (MLP=4) before any compute.
        const float4 ai0 = __ldg(&g_atoms[2 * p.x]);
        const float4 aj0 = __ldg(&g_atoms[2 * p.y]);
        const float4 ai1 = __ldg(&g_atoms[2 * p.z]);
        const float4 aj1 = __ldg(&g_atoms[2 * p.w]);

        // ---- pair 0 ----
        {
            float dx = ai0.x - aj0.x;
            float dy = ai0.y - aj0.y;
            float dz = ai0.z - aj0.z;
            dx -= bx * rintf(dx * ibx);
            dy -= by * rintf(dy * iby);
            dz -= bz * rintf(dz * ibz);
            const float r2 = fmaf(dx, dx, fmaf(dy, dy, dz * dz));
            if (r2 < CUTOFF2) {                       // cheap test first: skips divides for 99.7%
                if (((p.x / 3) != (p.y / 3)) && (p.x != p.y))
                    acc += pair_energy(p.x, p.y, r2, ai0.w, aj0.w);
            }
        }
        // ---- pair 1 ----
        {
            float dx = ai1.x - aj1.x;
            float dy = ai1.y - aj1.y;
            float dz = ai1.z - aj1.z;
            dx -= bx * rintf(dx * ibx);
            dy -= by * rintf(dy * iby);
            dz -= bz * rintf(dz * ibz);
            const float r2 = fmaf(dx, dx, fmaf(dy, dy, dz * dz));
            if (r2 < CUTOFF2) {
                if (((p.z / 3) != (p.w / 3)) && (p.z != p.w))
                    acc += pair_energy(p.z, p.w, r2, ai1.w, aj1.w);
            }
        }
    }

    // warp reduction
    #pragma unroll
    for (int off = 16; off > 0; off >>= 1)
        acc += __shfl_down_sync(0xFFFFFFFFu, acc, off);

    __shared__ float warp_sums[8];
    const int lane = threadIdx.x & 31;
    const int wid  = threadIdx.x >> 5;
    if (lane == 0) warp_sums[wid] = acc;
    __syncthreads();

    if (wid == 0) {
        float v = (lane < (blockDim.x >> 5)) ? warp_sums[lane] : 0.0f;
        #pragma unroll
        for (int off = 4; off > 0; off >>= 1)
            v += __shfl_down_sync(0xFFFFFFFFu, v, off);
        if (lane == 0)
            atomicAdd(out, v);
    }
}

extern "C" void kernel_launch(void* const* d_in, const int* in_sizes, int n_in,
                              void* d_out, int out_size)
{
    const float* coords  = (const float*)d_in[0];  // [N,3]
    const float* box     = (const float*)d_in[1];  // [3,3]
    const float* charges = (const float*)d_in[2];  // [N]
    const float* sigma   = (const float*)d_in[3];  // [N]
    const float* epsilon = (const float*)d_in[4];  // [N]
    const int4*  pairs2  = (const int4*)d_in[5];   // [NPAIRS,2] as [NPAIRS/2, 4]
    float* out = (float*)d_out;

    const int npairs2 = in_sizes[5] / 4;

    {
        const int threads = 256;
        const int blocks = (NATOMS + threads - 1) / threads;
        pack_kernel<<<blocks, threads>>>(coords, charges, sigma, epsilon, out);
    }
    {
        const int threads = 256;
        const int blocks = 4096;
        energy_kernel<<<blocks, threads>>>(pairs2, box, out, npairs2);
    }
}